// round 1
// baseline (speedup 1.0000x reference)
#include <cuda_runtime.h>
#include <math.h>

#define N_NODES 50000
#define N_EDGES 800000
#define EPS 0.01f
#define NSTEPS 10

// ---------------- scratch (device globals: no allocation allowed) ----------------
__device__ float  g_B[256 * 192];          // packed [Wt1 | Ws | Wd], row-major [k][j]
__device__ float  g_hid[N_NODES * 128];    // leaky_relu(node_emb@Wt1 + bt1)
__device__ float  g_hs[N_NODES * 32];      // node_emb @ Ws
__device__ float  g_hd[N_NODES * 32];      // node_emb @ Wd
__device__ float  g_elen[N_EDGES];
__device__ float  g_stepsz[N_EDGES];
__device__ float4 g_coords[N_NODES];
__device__ float4 g_aggr[N_NODES];

__device__ __forceinline__ float lrelu(float x) { return x > 0.f ? x : 0.01f * x; }

// ---------------- init: pack B, load coords, zero aggr ----------------
__global__ void init_k(const float* __restrict__ cart,
                       const float* __restrict__ Wt1,
                       const float* __restrict__ Wr1) {
    int i = blockIdx.x * blockDim.x + threadIdx.x;
    if (i < N_NODES) {
        g_coords[i] = make_float4(cart[3*i], cart[3*i+1], cart[3*i+2], 0.f);
        g_aggr[i]   = make_float4(0.f, 0.f, 0.f, 0.f);
    }
    if (i < 256 * 192) {
        int k = i / 192, j = i % 192;
        float v;
        if (j < 128)      v = Wt1[k * 128 + j];                 // torsion hidden cols
        else if (j < 160) v = Wr1[(64  + k) * 32 + (j - 128)];  // Ws rows 64..319
        else              v = Wr1[(320 + k) * 32 + (j - 160)];  // Wd rows 320..575
        g_B[i] = v;
    }
}

// ---------------- fused node GEMM: [M,256] x [256,192] ----------------
// Tile: 64 rows x 192 cols, BK=16. 256 threads, each owns 8x6 accumulators.
__global__ void node_gemm(const float* __restrict__ A, const float* __restrict__ bt1) {
    __shared__ float As[16 * 65];    // [k][m], padded stride 65
    __shared__ float Bs[16 * 192];   // [k][j]

    const int t  = threadIdx.x;
    const int tx = t & 31;           // col lane (0..31)
    const int ty = t >> 5;           // row group (0..7) -> one warp per ty
    const int m0 = blockIdx.x * 64;

    float acc[8][6];
#pragma unroll
    for (int r = 0; r < 8; r++)
#pragma unroll
        for (int c = 0; c < 6; c++) acc[r][c] = 0.f;

    const int lm = t >> 2;           // load row 0..63
    const int kq = t & 3;            // k quad
    const bool valid = (m0 + lm) < N_NODES;
    const float* Arow = A + (size_t)(m0 + lm) * 256 + kq * 4;

    for (int kt = 0; kt < 16; kt++) {
        float4 av = make_float4(0.f, 0.f, 0.f, 0.f);
        if (valid) av = *(const float4*)(Arow + kt * 16);
        As[(kq*4 + 0) * 65 + lm] = av.x;
        As[(kq*4 + 1) * 65 + lm] = av.y;
        As[(kq*4 + 2) * 65 + lm] = av.z;
        As[(kq*4 + 3) * 65 + lm] = av.w;

        const float4* Bp  = (const float4*)(g_B + kt * 16 * 192);
        float4*       Bs4 = (float4*)Bs;
        Bs4[t]       = Bp[t];
        Bs4[t + 256] = Bp[t + 256];
        Bs4[t + 512] = Bp[t + 512];
        __syncthreads();

#pragma unroll
        for (int kk = 0; kk < 16; kk++) {
            float a[8], b[6];
#pragma unroll
            for (int r = 0; r < 8; r++) a[r] = As[kk * 65 + ty + 8 * r];
#pragma unroll
            for (int c = 0; c < 6; c++) b[c] = Bs[kk * 192 + tx + 32 * c];
#pragma unroll
            for (int r = 0; r < 8; r++)
#pragma unroll
                for (int c = 0; c < 6; c++) acc[r][c] = fmaf(a[r], b[c], acc[r][c]);
        }
        __syncthreads();
    }

#pragma unroll
    for (int r = 0; r < 8; r++) {
        int m = m0 + ty + 8 * r;
        if (m >= N_NODES) continue;
#pragma unroll
        for (int c = 0; c < 6; c++) {
            int col = tx + 32 * c;
            float v = acc[r][c];
            if (col < 128) {
                g_hid[m * 128 + col] = lrelu(v + __ldg(&bt1[col]));
            } else if (col < 160) {
                g_hs[m * 32 + (col - 128)] = v;
            } else {
                g_hd[m * 32 + (col - 160)] = v;
            }
        }
    }
}

// ---------------- torsion finisher: warp per node ----------------
__global__ void torsion_k(const float* __restrict__ Wt2,
                          const float* __restrict__ bt2,
                          float* __restrict__ out) {
    int warp = (blockIdx.x * blockDim.x + threadIdx.x) >> 5;
    int lane = threadIdx.x & 31;
    if (warp >= N_NODES) return;

    float4 h = *(const float4*)(g_hid + warp * 128 + lane * 4);
    int base = (lane * 4) * 3;
    float t0 = h.x * __ldg(&Wt2[base+0]) + h.y * __ldg(&Wt2[base+3])
             + h.z * __ldg(&Wt2[base+6]) + h.w * __ldg(&Wt2[base+9]);
    float t1 = h.x * __ldg(&Wt2[base+1]) + h.y * __ldg(&Wt2[base+4])
             + h.z * __ldg(&Wt2[base+7]) + h.w * __ldg(&Wt2[base+10]);
    float t2 = h.x * __ldg(&Wt2[base+2]) + h.y * __ldg(&Wt2[base+5])
             + h.z * __ldg(&Wt2[base+8]) + h.w * __ldg(&Wt2[base+11]);

#pragma unroll
    for (int off = 16; off > 0; off >>= 1) {
        t0 += __shfl_down_sync(0xffffffffu, t0, off);
        t1 += __shfl_down_sync(0xffffffffu, t1, off);
        t2 += __shfl_down_sync(0xffffffffu, t2, off);
    }
    if (lane == 0) {
        t0 += __ldg(&bt2[0]); t1 += __ldg(&bt2[1]); t2 += __ldg(&bt2[2]);
        float rho = sqrtf(t0*t0 + t1*t1 + t2*t2);
        float theta = (fabsf(t0) > fabsf(t1)) ? atan2f(t1, t0)
                                              : (1.57079632679489662f - atan2f(t0, t1));
        float tn2 = t2 / rho;
        tn2 = fminf(fmaxf(tn2, -1.0f + EPS), 1.0f - EPS);
        float phi = acosf(tn2);
        float* o = out + 3 * N_NODES + warp * 3;   // torsion block follows coords
        o[0] = rho; o[1] = phi; o[2] = theta;
    }
}

// ---------------- edge MLP: 64 edges/block, K=64, 32 cols ----------------
__global__ void edge_mlp(const float* __restrict__ Eemb,
                         const float* __restrict__ Wr1,
                         const float* __restrict__ br1,
                         const float* __restrict__ Wr2,
                         const float* __restrict__ br2,
                         const int* __restrict__ eidx) {
    __shared__ float Ae[64 * 68];    // [edge][k], padded
    __shared__ float Ws[64 * 32];    // We = Wr1 rows 0..63
    __shared__ float Wr2s[64];

    const int t    = threadIdx.x;
    const int base = blockIdx.x * 64;

    {   // We is exactly the first 2048 floats of Wr1
        float4*       Ws4  = (float4*)Ws;
        const float4* W14  = (const float4*)Wr1;
        Ws4[t]       = W14[t];
        Ws4[t + 256] = W14[t + 256];
        if (t < 64) Wr2s[t] = Wr2[t];
    }
    {
        const float4* E4 = (const float4*)(Eemb + (size_t)base * 64);
#pragma unroll
        for (int i = 0; i < 4; i++) {
            int f = t + 256 * i;          // float4 index, 1024 total
            int e = f >> 4, kp = f & 15;
            *(float4*)&Ae[e * 68 + kp * 4] = E4[f];
        }
    }
    __syncthreads();

    const int x = t & 7;     // col group: cols x*4 .. x*4+3
    const int y = t >> 3;    // edge y and y+32

    float acc0[4] = {0.f,0.f,0.f,0.f};
    float acc1[4] = {0.f,0.f,0.f,0.f};

#pragma unroll
    for (int k = 0; k < 64; k += 4) {
        float4 a0 = *(const float4*)&Ae[y * 68 + k];
        float4 a1 = *(const float4*)&Ae[(y + 32) * 68 + k];
        float a0v[4] = {a0.x, a0.y, a0.z, a0.w};
        float a1v[4] = {a1.x, a1.y, a1.z, a1.w};
#pragma unroll
        for (int kk = 0; kk < 4; kk++) {
            float4 b = *(const float4*)&Ws[(k + kk) * 32 + x * 4];
            acc0[0] = fmaf(a0v[kk], b.x, acc0[0]);
            acc0[1] = fmaf(a0v[kk], b.y, acc0[1]);
            acc0[2] = fmaf(a0v[kk], b.z, acc0[2]);
            acc0[3] = fmaf(a0v[kk], b.w, acc0[3]);
            acc1[0] = fmaf(a1v[kk], b.x, acc1[0]);
            acc1[1] = fmaf(a1v[kk], b.y, acc1[1]);
            acc1[2] = fmaf(a1v[kk], b.z, acc1[2]);
            acc1[3] = fmaf(a1v[kk], b.w, acc1[3]);
        }
    }

    const float b2_0 = __ldg(&br2[0]);
    const float b2_1 = __ldg(&br2[1]);

#pragma unroll
    for (int half = 0; half < 2; half++) {
        int e = base + y + 32 * half;
        float* acc = half ? acc1 : acc0;
        int s = __ldg(&eidx[e]);
        int d = __ldg(&eidx[N_EDGES + e]);
        float4 hsv = *(const float4*)&g_hs[s * 32 + x * 4];
        float4 hdv = *(const float4*)&g_hd[d * 32 + x * 4];
        float hv[4];
        hv[0] = acc[0] + hsv.x + hdv.x + __ldg(&br1[x*4+0]);
        hv[1] = acc[1] + hsv.y + hdv.y + __ldg(&br1[x*4+1]);
        hv[2] = acc[2] + hsv.z + hdv.z + __ldg(&br1[x*4+2]);
        hv[3] = acc[3] + hsv.w + hdv.w + __ldg(&br1[x*4+3]);
        float p0 = 0.f, p1 = 0.f;
#pragma unroll
        for (int c = 0; c < 4; c++) {
            float hh = lrelu(hv[c]);
            p0 = fmaf(hh, Wr2s[(x*4 + c) * 2 + 0], p0);
            p1 = fmaf(hh, Wr2s[(x*4 + c) * 2 + 1], p1);
        }
        // reduce across the 8 lanes sharing this edge (width=8 segments)
        p0 += __shfl_down_sync(0xffffffffu, p0, 4, 8);
        p1 += __shfl_down_sync(0xffffffffu, p1, 4, 8);
        p0 += __shfl_down_sync(0xffffffffu, p0, 2, 8);
        p1 += __shfl_down_sync(0xffffffffu, p1, 2, 8);
        p0 += __shfl_down_sync(0xffffffffu, p0, 1, 8);
        p1 += __shfl_down_sync(0xffffffffu, p1, 1, 8);
        if (x == 0) {
            float elx = p0 + b2_0 + 1.0f;
            g_elen[e]  = (elx > 20.f) ? elx : log1pf(expf(elx));   // softplus
            float stx = p1 + b2_1 - 2.0f;
            g_stepsz[e] = 1.0f / (1.0f + expf(-stx));              // sigmoid
        }
    }
}

// ---------------- refiner: force + scatter, then node update ----------------
__global__ void force_k(const int* __restrict__ eidx) {
    int e = blockIdx.x * blockDim.x + threadIdx.x;
    if (e >= N_EDGES) return;
    int s = __ldg(&eidx[e]);
    int d = __ldg(&eidx[N_EDGES + e]);
    float4 cs = g_coords[s];
    float4 cd = g_coords[d];
    float dx = cd.x - cs.x, dy = cd.y - cs.y, dz = cd.z - cs.z;
    float dist = sqrtf(dx*dx + dy*dy + dz*dz);
    float coef = 2.0f * g_stepsz[e] * (g_elen[e] - dist) / (dist + EPS);
    atomicAdd(&g_aggr[d].x, coef * dx);
    atomicAdd(&g_aggr[d].y, coef * dy);
    atomicAdd(&g_aggr[d].z, coef * dz);
}

__global__ void update_k(float* __restrict__ out, int write_out) {
    int n = blockIdx.x * blockDim.x + threadIdx.x;
    if (n >= N_NODES) return;
    float4 a = g_aggr[n];
    float an = sqrtf(a.x*a.x + a.y*a.y + a.z*a.z) + EPS;
    float sc = fminf(an, 0.5f) / an;
    float4 c = g_coords[n];
    c.x += a.x * sc; c.y += a.y * sc; c.z += a.z * sc;
    g_coords[n] = c;
    g_aggr[n] = make_float4(0.f, 0.f, 0.f, 0.f);
    if (write_out) {
        out[n * 3 + 0] = c.x;
        out[n * 3 + 1] = c.y;
        out[n * 3 + 2] = c.z;
    }
}

// ---------------- launch ----------------
extern "C" void kernel_launch(void* const* d_in, const int* in_sizes, int n_in,
                              void* d_out, int out_size) {
    const float* node_emb = (const float*)d_in[0];
    const float* edge_emb = (const float*)d_in[1];
    const float* cart     = (const float*)d_in[2];
    const float* Wt1      = (const float*)d_in[3];
    const float* bt1      = (const float*)d_in[4];
    const float* Wt2      = (const float*)d_in[5];
    const float* bt2      = (const float*)d_in[6];
    const float* Wr1      = (const float*)d_in[7];
    const float* br1      = (const float*)d_in[8];
    const float* Wr2      = (const float*)d_in[9];
    const float* br2      = (const float*)d_in[10];
    const int*   eidx     = (const int*)d_in[11];
    float* out = (float*)d_out;

    init_k<<<(N_NODES + 255) / 256, 256>>>(cart, Wt1, Wr1);
    node_gemm<<<(N_NODES + 63) / 64, 256>>>(node_emb, bt1);
    torsion_k<<<N_NODES / 4, 128>>>(Wt2, bt2, out);
    edge_mlp<<<N_EDGES / 64, 256>>>(edge_emb, Wr1, br1, Wr2, br2, eidx);
    for (int it = 0; it < NSTEPS; it++) {
        force_k<<<(N_EDGES + 255) / 256, 256>>>(eidx);
        update_k<<<(N_NODES + 255) / 256, 256>>>(out, it == NSTEPS - 1);
    }
}